// round 12
// baseline (speedup 1.0000x reference)
#include <cuda_runtime.h>
#include <cstdint>

// 2-layer LSTM, H=6, F=6, B=4096, T=1024.  Base = R9 (best, 226us):
// 2 elems/warp, 12 active lanes/elem: lane (l,k) owns hidden k of layer l,
// K-packed f32x2 matvec, smem h-exchange (double-buffered slots).
// R12 changes:
//  (a) activations via ex2+rcp (MUFU rt=8 documented) instead of tanh.approx:
//      sigmoid rows pre-scaled by -log2(e), g rows by -2log2(e).
//  (b) x staging split: LDG->regs issued one chunk early (latency hidden
//      under compute), STS at loop top. No exposed global stalls.

#define WARPS_PER_BLOCK 14
#define THREADS (WARPS_PER_BLOCK * 32)
#define T_LEN 1024
#define TCHUNK 16
#define NCHUNK (T_LEN / TCHUNK)     // 64
#define CSTRIDE 104                 // floats per elem per chunk (96 data + 8 pad)
#define CSTRIDE4 (CSTRIDE / 4)      // 26

#define L2E 1.4426950408889634f
#define NSL (-L2E)
#define NS2 (-2.0f * L2E)

typedef unsigned long long ull;

__device__ __forceinline__ float ex2f(float x) {
    float y; asm("ex2.approx.f32 %0, %1;" : "=f"(y) : "f"(x)); return y;
}
__device__ __forceinline__ float rcpf(float x) {
    float y; asm("rcp.approx.f32 %0, %1;" : "=f"(y) : "f"(x)); return y;
}
__device__ __forceinline__ ull pk2(float lo, float hi) {
    ull r; asm("mov.b64 %0, {%1, %2};" : "=l"(r) : "f"(lo), "f"(hi)); return r;
}
__device__ __forceinline__ void upk2(float& lo, float& hi, ull v) {
    asm("mov.b64 {%0, %1}, %2;" : "=f"(lo), "=f"(hi) : "l"(v));
}
__device__ __forceinline__ ull fma2(ull a, ull b, ull c) {
    ull d; asm("fma.rn.f32x2 %0, %1, %2, %3;" : "=l"(d) : "l"(a), "l"(b), "l"(c));
    return d;
}
__device__ __forceinline__ ull lds64(uint32_t addr) {
    ull v; asm volatile("ld.shared.b64 %0, [%1];" : "=l"(v) : "r"(addr));
    return v;
}
__device__ __forceinline__ void sts32(uint32_t addr, float v) {
    asm volatile("st.shared.f32 [%0], %1;" :: "r"(addr), "f"(v) : "memory");
}

__global__ __launch_bounds__(THREADS, 1)
void lstm2_kernel(const float* __restrict__ x,
                  const float* __restrict__ wih0, const float* __restrict__ whh0,
                  const float* __restrict__ bih0, const float* __restrict__ bhh0,
                  const float* __restrict__ wih1, const float* __restrict__ whh1,
                  const float* __restrict__ bih1, const float* __restrict__ bhh1,
                  float* __restrict__ out, int B)
{
    __shared__ float sx[2][WARPS_PER_BLOCK][2 * CSTRIDE];
    __shared__ float soB[WARPS_PER_BLOCK][2 * CSTRIDE];
    __shared__ float hx[WARPS_PER_BLOCK][96];   // e*48 + slot*20 + l*8 + k

    const int lane = threadIdx.x & 31;
    const int warp = threadIdx.x >> 5;
    const int e    = lane >> 4;
    const int s    = lane & 15;
    const int l    = (s >= 6 && s < 12) ? 1 : 0;
    const int k    = (s < 6) ? s : ((s < 12) ? s - 6 : 0);
    const bool wr  = (s >= 6 && s < 12);

    const int b0 = (blockIdx.x * WARPS_PER_BLOCK + warp) * 2;
    if (b0 >= B) return;

    // ---- K-packed per-lane weights, pre-scaled for ex2-based activations ----
    const float* wih = l ? wih1 : wih0;
    const float* whh = l ? whh1 : whh0;
    const float* bih = l ? bih1 : bih0;
    const float* bhh = l ? bhh1 : bhh0;

    ull wx[4][3], wh[4][3], bz[4];
#pragma unroll
    for (int g = 0; g < 4; g++) {
        const float sc = (g == 2) ? NS2 : NSL;   // g row: -2log2e; sigmoid rows: -log2e
        const int row = g * 6 + k;
#pragma unroll
        for (int p = 0; p < 3; p++) {
            wx[g][p] = pk2(wih[row * 6 + 2 * p] * sc, wih[row * 6 + 2 * p + 1] * sc);
            wh[g][p] = pk2(whh[row * 6 + 2 * p] * sc, whh[row * 6 + 2 * p + 1] * sc);
        }
        bz[g] = pk2((bih[row] + bhh[row]) * sc, 0.0f);
    }

    // ---- smem addresses ----
    const uint32_t hx_u  = (uint32_t)__cvta_generic_to_shared(&hx[warp][0]);
    const uint32_t hxe_u = hx_u + e * 192;
    const uint32_t recO  = hxe_u + l * 32;
    const uint32_t recE  = recO + 80;
    const uint32_t stO   = hxe_u + ((s < 12) ? (l * 8 + k) * 4 : 56);
    const uint32_t stE   = stO + 80;
    uint32_t sx_u[2];
    sx_u[0] = (uint32_t)__cvta_generic_to_shared(&sx[0][warp][0]);
    sx_u[1] = (uint32_t)__cvta_generic_to_shared(&sx[1][warp][0]);

    hx[warp][lane] = 0.0f; hx[warp][lane + 32] = 0.0f; hx[warp][lane + 64] = 0.0f;
    __syncwarp();

    float cc = 0.0f;

    // ---- split staging: LDG into regs (early), STS later ----
    float4 xr4[2];
    auto ldg_chunk = [&](int c) {
#pragma unroll
        for (int i = 0; i < 2; i++) {
            int idx = i * 32 + lane;
            if (idx < 48) {
                int ee  = idx / 24;
                int off = idx - ee * 24;
                xr4[i] = *reinterpret_cast<const float4*>(
                    x + (size_t)(b0 + ee) * (T_LEN * 6) + c * (TCHUNK * 6) + 4 * off);
            }
        }
    };
    auto sts_chunk = [&](int buf) {
        float4* dst = reinterpret_cast<float4*>(sx[buf][warp]);
#pragma unroll
        for (int i = 0; i < 2; i++) {
            int idx = i * 32 + lane;
            if (idx < 48) {
                int ee  = idx / 24;
                int off = idx - ee * 24;
                dst[ee * CSTRIDE4 + off] = xr4[i];
            }
        }
    };

    // one step: inp addr ia, rec addr ra, write addr wa; stores h1 if dt>=0
    auto step = [&](uint32_t ia, uint32_t ra, uint32_t wa, int dt) {
        const ull v0 = lds64(ia), v1 = lds64(ia + 8), v2 = lds64(ia + 16);
        const ull r0 = lds64(ra), r1 = lds64(ra + 8), r2 = lds64(ra + 16);

        ull z0 = fma2(wx[0][0], v0, bz[0]);
        ull z1 = fma2(wx[1][0], v0, bz[1]);
        ull z2 = fma2(wx[2][0], v0, bz[2]);
        ull z3 = fma2(wx[3][0], v0, bz[3]);
        z0 = fma2(wx[0][1], v1, z0); z1 = fma2(wx[1][1], v1, z1);
        z2 = fma2(wx[2][1], v1, z2); z3 = fma2(wx[3][1], v1, z3);
        z0 = fma2(wx[0][2], v2, z0); z1 = fma2(wx[1][2], v2, z1);
        z2 = fma2(wx[2][2], v2, z2); z3 = fma2(wx[3][2], v2, z3);
        z0 = fma2(wh[0][0], r0, z0); z1 = fma2(wh[1][0], r0, z1);
        z2 = fma2(wh[2][0], r0, z2); z3 = fma2(wh[3][0], r0, z3);
        z0 = fma2(wh[0][1], r1, z0); z1 = fma2(wh[1][1], r1, z1);
        z2 = fma2(wh[2][1], r1, z2); z3 = fma2(wh[3][1], r1, z3);
        z0 = fma2(wh[0][2], r2, z0); z1 = fma2(wh[1][2], r2, z1);
        z2 = fma2(wh[2][2], r2, z2); z3 = fma2(wh[3][2], r2, z3);

        float a, b2;
        upk2(a, b2, z0); const float zi = a + b2;
        upk2(a, b2, z1); const float zf = a + b2;
        upk2(a, b2, z2); const float zg = a + b2;
        upk2(a, b2, z3); const float zo = a + b2;

        // ex2-based activations (weights pre-scaled): sigma = rcp(1+ex2(z'))
        const float gi = rcpf(1.0f + ex2f(zi));
        const float gf = rcpf(1.0f + ex2f(zf));
        const float gg = fmaf(2.0f, rcpf(1.0f + ex2f(zg)), -1.0f);
        const float go = rcpf(1.0f + ex2f(zo));

        cc = fmaf(gf, cc, gi * gg);
        const float th = fmaf(2.0f, rcpf(1.0f + ex2f(cc * NS2)), -1.0f);
        const float hn = go * th;

        sts32(wa, hn);
        if (dt >= 0 && wr) soB[warp][e * CSTRIDE + dt * 6 + k] = hn;
        __syncwarp();
    };

    // ---- prologue: stage chunk 0; LDG chunk 1 early; step 0 ----
    ldg_chunk(0);
    sts_chunk(0);
    __syncwarp();
    ldg_chunk(1);                       // in flight under prologue + chunk 0
    {
        const uint32_t ia = l ? (hxe_u + 0) : (sx_u[0] + e * 416 + 0);
        step(ia, recO, stE, -1);
        if (l) { cc = 0.0f; sts32(stE, 0.0f); }
        __syncwarp();
    }

    // ---- main loop: chunk c covers main steps m = c*16+1 .. c*16+16 ----
    for (int c = 0; c < NCHUNK; c++) {
        if (c + 1 < NCHUNK) sts_chunk((c + 1) & 1);   // regs hold chunk c+1
        if (c + 2 < NCHUNK) ldg_chunk(c + 2);         // hide LDG under compute

        const uint32_t xb = sx_u[c & 1] + e * 416;
        const uint32_t xn = sx_u[(c + 1) & 1] + e * 416;
        uint32_t inpE = l ? (hxe_u + 80) : (xb + 24);   // even dt: read slot1
        uint32_t inpO = l ? (hxe_u +  0) : (xb + 48);   // odd dt: read slot0
        const uint32_t inpLast = l ? (hxe_u + 0) : xn;  // dt=15 reads next chunk
        const uint32_t sI = l ? 0u : 48u;

#pragma unroll
        for (int dt = 0; dt < TCHUNK; dt += 2) {
            step(inpE, recE, stO, dt);
            const uint32_t ia = (dt + 1 == TCHUNK - 1) ? inpLast : inpO;
            step(ia, recO, stE, dt + 1);
            inpE += sI; inpO += sI;
        }

        // ---- flush h1 outputs for t in [c*16, c*16+16) ----
        {
            const float4* src = reinterpret_cast<const float4*>(soB[warp]);
#pragma unroll
            for (int i = 0; i < 2; i++) {
                int idx = i * 32 + lane;
                if (idx < 48) {
                    int ee  = idx / 24;
                    int off = idx - ee * 24;
                    float4* dst = reinterpret_cast<float4*>(
                        out + (size_t)(b0 + ee) * (T_LEN * 6) + c * (TCHUNK * 6));
                    dst[off] = src[ee * CSTRIDE4 + off];
                }
            }
        }
        __syncwarp();
    }
}

extern "C" void kernel_launch(void* const* d_in, const int* in_sizes, int n_in,
                              void* d_out, int out_size)
{
    const float* x    = (const float*)d_in[0];
    const float* wih0 = (const float*)d_in[1];
    const float* whh0 = (const float*)d_in[2];
    const float* bih0 = (const float*)d_in[3];
    const float* bhh0 = (const float*)d_in[4];
    const float* wih1 = (const float*)d_in[5];
    const float* whh1 = (const float*)d_in[6];
    const float* bih1 = (const float*)d_in[7];
    const float* bhh1 = (const float*)d_in[8];
    float* out = (float*)d_out;

    const int B = in_sizes[0] / (T_LEN * 6);                                 // 4096
    const int grid = (B + 2 * WARPS_PER_BLOCK - 1) / (2 * WARPS_PER_BLOCK);  // 147

    lstm2_kernel<<<grid, THREADS>>>(x, wih0, whh0, bih0, bhh0,
                                    wih1, whh1, bih1, bhh1, out, B);
}

// round 13
// speedup vs baseline: 1.3504x; 1.3504x over previous
#include <cuda_runtime.h>
#include <cstdint>

// 2-layer LSTM, H=6, F=6, B=4096, T=1024.  Base = R9 (best, 226us):
// 2 elems/warp, 12 active lanes/elem: lane (l,k) owns hidden k of layer l,
// K-packed f32x2 matvec, smem h-exchange (double-buffered slots), tanh.approx.
// R13 changes:
//  (1) z split into v-chain / rec-chain (depth 12 -> 3+3 fma2 + add2)
//  (2) x staged at 32B/step + 16B-aligned rec slots -> LDS.128+LDS.64 pairs
//  (3) LDG->reg prefetch staging one chunk ahead (no exposed global stalls)

#define WARPS_PER_BLOCK 14
#define THREADS (WARPS_PER_BLOCK * 32)
#define T_LEN 1024
#define TCHUNK 16
#define NCHUNK (T_LEN / TCHUNK)     // 64
#define XSTR 132                    // floats per elem per chunk in sx (16 steps x 8 + pad)
#define OSTR 104                    // floats per elem per chunk in soB
#define OSTR4 (OSTR / 4)            // 26

typedef unsigned long long ull;

__device__ __forceinline__ float tanha(float x) {
    float y; asm("tanh.approx.f32 %0, %1;" : "=f"(y) : "f"(x)); return y;
}
__device__ __forceinline__ ull pk2(float lo, float hi) {
    ull r; asm("mov.b64 %0, {%1, %2};" : "=l"(r) : "f"(lo), "f"(hi)); return r;
}
__device__ __forceinline__ void upk2(float& lo, float& hi, ull v) {
    asm("mov.b64 {%0, %1}, %2;" : "=f"(lo), "=f"(hi) : "l"(v));
}
__device__ __forceinline__ ull fma2(ull a, ull b, ull c) {
    ull d; asm("fma.rn.f32x2 %0, %1, %2, %3;" : "=l"(d) : "l"(a), "l"(b), "l"(c));
    return d;
}
__device__ __forceinline__ ull mul2(ull a, ull b) {
    ull d; asm("mul.rn.f32x2 %0, %1, %2;" : "=l"(d) : "l"(a), "l"(b));
    return d;
}
__device__ __forceinline__ ull add2(ull a, ull b) {
    ull d; asm("add.rn.f32x2 %0, %1, %2;" : "=l"(d) : "l"(a), "l"(b));
    return d;
}
__device__ __forceinline__ ull lds64(uint32_t addr) {
    ull v; asm volatile("ld.shared.b64 %0, [%1];" : "=l"(v) : "r"(addr));
    return v;
}
__device__ __forceinline__ void lds128p(uint32_t addr, ull& a, ull& b) {
    asm volatile("ld.shared.v2.b64 {%0, %1}, [%2];" : "=l"(a), "=l"(b) : "r"(addr));
}
__device__ __forceinline__ void sts32(uint32_t addr, float v) {
    asm volatile("st.shared.f32 [%0], %1;" :: "r"(addr), "f"(v) : "memory");
}
__device__ __forceinline__ void sts64(uint32_t addr, float2 v) {
    asm volatile("st.shared.v2.f32 [%0], {%1, %2};"
                 :: "r"(addr), "f"(v.x), "f"(v.y) : "memory");
}

__global__ __launch_bounds__(THREADS, 1)
void lstm2_kernel(const float* __restrict__ x,
                  const float* __restrict__ wih0, const float* __restrict__ whh0,
                  const float* __restrict__ bih0, const float* __restrict__ bhh0,
                  const float* __restrict__ wih1, const float* __restrict__ whh1,
                  const float* __restrict__ bih1, const float* __restrict__ bhh1,
                  float* __restrict__ out, int B)
{
    __shared__ __align__(16) float sx[2][WARPS_PER_BLOCK][2 * XSTR];
    __shared__ __align__(16) float soB[WARPS_PER_BLOCK][2 * OSTR];
    __shared__ __align__(16) float hx[WARPS_PER_BLOCK][96];  // e*48f + slot*20f + l*8f + k

    const int lane = threadIdx.x & 31;
    const int warp = threadIdx.x >> 5;
    const int e    = lane >> 4;
    const int s    = lane & 15;
    const int l    = (s >= 6 && s < 12) ? 1 : 0;
    const int k    = (s < 6) ? s : ((s < 12) ? s - 6 : 0);
    const bool wr  = (s >= 6 && s < 12);

    const int b0 = (blockIdx.x * WARPS_PER_BLOCK + warp) * 2;
    if (b0 >= B) return;

    // ---- K-packed per-lane weights; sigmoid rows pre-scaled by 0.5 ----
    const float* wih = l ? wih1 : wih0;
    const float* whh = l ? whh1 : whh0;
    const float* bih = l ? bih1 : bih0;
    const float* bhh = l ? bhh1 : bhh0;

    ull wx[4][3], wh[4][3], bz[4];
#pragma unroll
    for (int g = 0; g < 4; g++) {
        const float sc = (g == 2) ? 1.0f : 0.5f;
        const int row = g * 6 + k;
#pragma unroll
        for (int p = 0; p < 3; p++) {
            wx[g][p] = pk2(wih[row * 6 + 2 * p] * sc, wih[row * 6 + 2 * p + 1] * sc);
            wh[g][p] = pk2(whh[row * 6 + 2 * p] * sc, whh[row * 6 + 2 * p + 1] * sc);
        }
        bz[g] = pk2((bih[row] + bhh[row]) * sc, 0.0f);
    }

    // ---- smem addresses ----
    const uint32_t hx_u  = (uint32_t)__cvta_generic_to_shared(&hx[warp][0]);
    const uint32_t hxe_u = hx_u + e * 192;
    const uint32_t recO  = hxe_u + l * 32;       // 16B-aligned
    const uint32_t recE  = recO + 80;            // 16B-aligned
    const uint32_t stO   = hxe_u + ((s < 12) ? (l * 8 + k) * 4 : 56);
    const uint32_t stE   = stO + 80;
    uint32_t sx_u[2];
    sx_u[0] = (uint32_t)__cvta_generic_to_shared(&sx[0][warp][0]);
    sx_u[1] = (uint32_t)__cvta_generic_to_shared(&sx[1][warp][0]);

    hx[warp][lane] = 0.0f; hx[warp][lane + 32] = 0.0f; hx[warp][lane + 64] = 0.0f;
    __syncwarp();

    float cc = 0.0f;

    // ---- LDG->reg prefetch staging: 96 float2 per warp (3 per lane) ----
    // idx = i*32+lane: ee=idx/48, r=idx%48, step=r/3, pair=r%3
    float2 xr2[3];
    int st_i[3], ee_i[3], pr_i[3];
#pragma unroll
    for (int i = 0; i < 3; i++) {
        int idx = i * 32 + lane;
        ee_i[i] = idx / 48;
        int r = idx - ee_i[i] * 48;
        st_i[i] = r / 3;
        pr_i[i] = r - st_i[i] * 3;
    }
    auto ldg_chunk = [&](int c) {
#pragma unroll
        for (int i = 0; i < 3; i++) {
            xr2[i] = *reinterpret_cast<const float2*>(
                x + (size_t)(b0 + ee_i[i]) * (T_LEN * 6) + c * (TCHUNK * 6)
                  + st_i[i] * 6 + pr_i[i] * 2);
        }
    };
    auto sts_chunk = [&](int buf) {
#pragma unroll
        for (int i = 0; i < 3; i++) {
            sts64(sx_u[buf] + (uint32_t)(ee_i[i] * (XSTR * 4)
                  + st_i[i] * 32 + pr_i[i] * 8), xr2[i]);
        }
    };

    // one step: inp addr ia, rec addr ra, write addr wa; stores h1 if dt>=0
    auto step = [&](uint32_t ia, uint32_t ra, uint32_t wa, int dt) {
        ull v0, v1, r0, r1;
        lds128p(ia, v0, v1);
        const ull v2 = lds64(ia + 16);
        lds128p(ra, r0, r1);
        const ull r2 = lds64(ra + 16);

        // v-chain (bias-seeded) and rec-chain, 3 deep each, combined with add2
        ull a0 = fma2(wx[0][0], v0, bz[0]);
        ull a1 = fma2(wx[1][0], v0, bz[1]);
        ull a2 = fma2(wx[2][0], v0, bz[2]);
        ull a3 = fma2(wx[3][0], v0, bz[3]);
        ull c0 = mul2(wh[0][0], r0);
        ull c1 = mul2(wh[1][0], r0);
        ull c2 = mul2(wh[2][0], r0);
        ull c3 = mul2(wh[3][0], r0);
        a0 = fma2(wx[0][1], v1, a0); a1 = fma2(wx[1][1], v1, a1);
        a2 = fma2(wx[2][1], v1, a2); a3 = fma2(wx[3][1], v1, a3);
        c0 = fma2(wh[0][1], r1, c0); c1 = fma2(wh[1][1], r1, c1);
        c2 = fma2(wh[2][1], r1, c2); c3 = fma2(wh[3][1], r1, c3);
        a0 = fma2(wx[0][2], v2, a0); a1 = fma2(wx[1][2], v2, a1);
        a2 = fma2(wx[2][2], v2, a2); a3 = fma2(wx[3][2], v2, a3);
        c0 = fma2(wh[0][2], r2, c0); c1 = fma2(wh[1][2], r2, c1);
        c2 = fma2(wh[2][2], r2, c2); c3 = fma2(wh[3][2], r2, c3);

        float a, b2;
        upk2(a, b2, add2(a0, c0)); const float zi = a + b2;
        upk2(a, b2, add2(a1, c1)); const float zf = a + b2;
        upk2(a, b2, add2(a2, c2)); const float zg = a + b2;
        upk2(a, b2, add2(a3, c3)); const float zo = a + b2;

        const float gi = fmaf(0.5f, tanha(zi), 0.5f);
        const float gf = fmaf(0.5f, tanha(zf), 0.5f);
        const float gg = tanha(zg);
        const float go = fmaf(0.5f, tanha(zo), 0.5f);

        cc = fmaf(gf, cc, gi * gg);
        const float hn = go * tanha(cc);

        sts32(wa, hn);
        if (dt >= 0 && wr) soB[warp][e * OSTR + dt * 6 + k] = hn;
        __syncwarp();
    };

    // ---- prologue: stage chunk 0; LDG chunk 1 early; step 0 ----
    ldg_chunk(0);
    sts_chunk(0);
    __syncwarp();
    ldg_chunk(1);
    {
        const uint32_t ia = l ? (hxe_u + 0) : (sx_u[0] + e * (XSTR * 4));
        step(ia, recO, stE, -1);
        if (l) { cc = 0.0f; sts32(stE, 0.0f); }
        __syncwarp();
    }

    // ---- main loop: chunk c covers main steps m = c*16+1 .. c*16+16 ----
    for (int c = 0; c < NCHUNK; c++) {
        if (c + 1 < NCHUNK) sts_chunk((c + 1) & 1);
        if (c + 2 < NCHUNK) ldg_chunk(c + 2);

        const uint32_t xb = sx_u[c & 1] + e * (XSTR * 4);
        const uint32_t xn = sx_u[(c + 1) & 1] + e * (XSTR * 4);
        uint32_t inpE = l ? (hxe_u + 80) : (xb + 32);    // even dt: read slot1
        uint32_t inpO = l ? (hxe_u +  0) : (xb + 64);    // odd dt: read slot0
        const uint32_t inpLast = l ? (hxe_u + 0) : xn;   // dt=15 reads next chunk
        const uint32_t sI = l ? 0u : 64u;

#pragma unroll
        for (int dt = 0; dt < TCHUNK; dt += 2) {
            step(inpE, recE, stO, dt);
            const uint32_t ia = (dt + 1 == TCHUNK - 1) ? inpLast : inpO;
            step(ia, recO, stE, dt + 1);
            inpE += sI; inpO += sI;
        }

        // ---- flush h1 outputs for t in [c*16, c*16+16) ----
        {
            const float4* src = reinterpret_cast<const float4*>(soB[warp]);
#pragma unroll
            for (int i = 0; i < 2; i++) {
                int idx = i * 32 + lane;
                if (idx < 48) {
                    int ee  = idx / 24;
                    int off = idx - ee * 24;
                    float4* dst = reinterpret_cast<float4*>(
                        out + (size_t)(b0 + ee) * (T_LEN * 6) + c * (TCHUNK * 6));
                    dst[off] = src[ee * OSTR4 + off];
                }
            }
        }
        __syncwarp();
    }
}

extern "C" void kernel_launch(void* const* d_in, const int* in_sizes, int n_in,
                              void* d_out, int out_size)
{
    const float* x    = (const float*)d_in[0];
    const float* wih0 = (const float*)d_in[1];
    const float* whh0 = (const float*)d_in[2];
    const float* bih0 = (const float*)d_in[3];
    const float* bhh0 = (const float*)d_in[4];
    const float* wih1 = (const float*)d_in[5];
    const float* whh1 = (const float*)d_in[6];
    const float* bih1 = (const float*)d_in[7];
    const float* bhh1 = (const float*)d_in[8];
    float* out = (float*)d_out;

    const int B = in_sizes[0] / (T_LEN * 6);                                 // 4096
    const int grid = (B + 2 * WARPS_PER_BLOCK - 1) / (2 * WARPS_PER_BLOCK);  // 147

    lstm2_kernel<<<grid, THREADS>>>(x, wih0, whh0, bih0, bhh0,
                                    wih1, whh1, bih1, bhh1, out, B);
}